// round 2
// baseline (speedup 1.0000x reference)
#include <cuda_runtime.h>

#define Nn   128
#define Hh   2
#define Ll   1024
#define Cc   (Hh * Ll)      /* 2048 columns = h*L flattened */
#define PRED (Nn * Cc)      /* 262144 */

#define SA_LD 132           /* padded lead dim for Amat tile (32 x 128) */
#define SB_LD 68            /* padded lead dim for alpha tile (128 x 64) */

__device__ float g_alpha[PRED];
__device__ float g_Ss[PRED];

// ---- packed fp32x2 helpers (sm_103a FFMA2 path, PTX-only) ------------------
__device__ __forceinline__ unsigned long long pack2(float lo, float hi) {
    unsigned long long r;
    asm("mov.b64 %0, {%1, %2};" : "=l"(r) : "f"(lo), "f"(hi));
    return r;
}
__device__ __forceinline__ void unpack2(unsigned long long v, float& lo, float& hi) {
    asm("mov.b64 {%0, %1}, %2;" : "=f"(lo), "=f"(hi) : "l"(v));
}
__device__ __forceinline__ unsigned long long ffma2(unsigned long long a,
                                                    unsigned long long b,
                                                    unsigned long long c) {
    unsigned long long d;
    asm("fma.rn.f32x2 %0, %1, %2, %3;" : "=l"(d) : "l"(a), "l"(b), "l"(c));
    return d;
}

// ---------------------------------------------------------------------------
// Kernel 1: per-(n,h)-row fused relu + cumsum + exponential-decay recurrence.
// 256 blocks (one per row), 128 threads, 8 contiguous elements per thread.
// ---------------------------------------------------------------------------
__global__ void __launch_bounds__(128) scan_kernel(const float* __restrict__ x,
                                                   const float* __restrict__ taus,
                                                   const float* __restrict__ r0dt,
                                                   float* __restrict__ out)
{
    int row  = blockIdx.x;          // n*H + h
    int t    = threadIdx.x;         // 0..127
    int lane = t & 31, wid = t >> 5;
    int base = row * Ll + t * 8;

    const float4* xv = reinterpret_cast<const float4*>(x + base);
    float4 v0 = xv[0], v1 = xv[1];
    float s[8] = { fmaxf(v0.x, 0.f), fmaxf(v0.y, 0.f), fmaxf(v0.z, 0.f), fmaxf(v0.w, 0.f),
                   fmaxf(v1.x, 0.f), fmaxf(v1.y, 0.f), fmaxf(v1.z, 0.f), fmaxf(v1.w, 0.f) };

    float tau = taus[row];
    float R0  = r0dt[row];
    float d   = 1.f - 1.f / tau;

    float cum = 0.f, isv = 0.f;
#pragma unroll
    for (int k = 0; k < 8; k++) { cum += s[k]; isv = fmaf(d, isv, s[k]); }

    float d2 = d * d, d4 = d2 * d2, r8 = d4 * d4;   // d^8

    float inclI = isv, inclC = cum, rp = r8;
#pragma unroll
    for (int off = 1; off < 32; off <<= 1) {
        float ui = __shfl_up_sync(0xffffffffu, inclI, off);
        float uc = __shfl_up_sync(0xffffffffu, inclC, off);
        if (lane >= off) { inclI = fmaf(rp, ui, inclI); inclC += uc; }
        rp *= rp;
    }

    __shared__ float wI[4], wC[4];
    if (lane == 31) { wI[wid] = inclI; wC[wid] = inclC; }
    __syncthreads();

    float Rw = rp;                                  // d^256
    float exI = 0.f, exC = 0.f, aI = 0.f, aC = 0.f;
#pragma unroll
    for (int w = 0; w < 4; w++) {
        if (w == wid) { exI = aI; exC = aC; }
        aI = fmaf(Rw, aI, wI[w]);
        aC += wC[w];
    }

    float upI = __shfl_up_sync(0xffffffffu, inclI, 1);
    float upC = __shfl_up_sync(0xffffffffu, inclC, 1);
    if (lane == 0) { upI = 0.f; upC = 0.f; }
    float XI = fmaf(exI, __powf(r8, (float)lane), upI);
    float XC = upC + exC;

    float al[8], ss[8];
    float ci = XI, cc = XC;
#pragma unroll
    for (int k = 0; k < 8; k++) {
        ci = fmaf(d, ci, s[k]);
        cc += s[k];
        al[k] = 1.f - __expf(-R0 * ci);
        ss[k] = 1.f - cc;
    }

    float4* ga = reinterpret_cast<float4*>(g_alpha + base);
    ga[0] = make_float4(al[0], al[1], al[2], al[3]);
    ga[1] = make_float4(al[4], al[5], al[6], al[7]);
    float4* gs = reinterpret_cast<float4*>(g_Ss + base);
    gs[0] = make_float4(ss[0], ss[1], ss[2], ss[3]);
    gs[1] = make_float4(ss[4], ss[5], ss[6], ss[7]);
    float4* go = reinterpret_cast<float4*>(out + PRED + base);   // signal output
    go[0] = make_float4(s[0], s[1], s[2], s[3]);
    go[1] = make_float4(s[4], s[5], s[6], s[7]);
}

// ---------------------------------------------------------------------------
// Kernel 2: Alpha = alpha + Amat @ alpha ;  pred = Alpha * Ss ; plus Amat + I.
// Grid (32 col-tiles x 4 row-tiles); block tile 32 rows x 64 cols; 512 threads,
// thread tile 1 row x 4 cols, accumulated as 2 packed f32x2 (FFMA2).
// ---------------------------------------------------------------------------
__global__ void __launch_bounds__(512) gemm_kernel(const float* __restrict__ Amat,
                                                   float* __restrict__ out)
{
    extern __shared__ float sm[];
    float* sA = sm;                  // [32][SA_LD]: rows k0..k0+31, all 128 m
    float* sB = sm + 32 * SA_LD;     // [128][SB_LD]: all m, 64 local cols

    int bx = blockIdx.x;             // 64-col tile (0..31)
    int by = blockIdx.y;             // 32-row tile (0..3)
    int tid = threadIdx.x;
    int k0 = by * 32, c0 = bx * 64;

#pragma unroll
    for (int i = tid; i < 32 * 128; i += 512) {
        int k = i >> 7, m = i & 127;
        sA[k * SA_LD + m] = Amat[(k0 + k) * 128 + m];
    }
#pragma unroll
    for (int i = tid; i < 128 * 16; i += 512) {
        int m = i >> 4, cq = i & 15;
        float4 v = *reinterpret_cast<const float4*>(&g_alpha[m * Cc + c0 + cq * 4]);
        *reinterpret_cast<float4*>(&sB[m * SB_LD + cq * 4]) = v;
    }
    __syncthreads();

    int tx = tid & 15;               // col quad: local cols tx*4 .. +3
    int ty = tid >> 4;               // local row 0..31
    int cl = tx * 4;

    // identity term: Alpha = alpha + Amat@alpha  (row k0+ty lives in sB too)
    float4 i0 = *reinterpret_cast<float4*>(&sB[(k0 + ty) * SB_LD + cl]);
    unsigned long long acc0 = pack2(i0.x, i0.y);
    unsigned long long acc1 = pack2(i0.z, i0.w);

    const float* aRow = &sA[ty * SA_LD];
#pragma unroll 8
    for (int m = 0; m < 128; m++) {
        float4 bv = *reinterpret_cast<float4*>(&sB[m * SB_LD + cl]);
        float a = aRow[m];
        unsigned long long ap = pack2(a, a);
        acc0 = ffma2(ap, pack2(bv.x, bv.y), acc0);
        acc1 = ffma2(ap, pack2(bv.z, bv.w), acc1);
    }

    int gk = k0 + ty;
    const float4 ssv = *reinterpret_cast<const float4*>(&g_Ss[gk * Cc + c0 + cl]);
    float r0, r1, r2, r3;
    unpack2(acc0, r0, r1);
    unpack2(acc1, r2, r3);
    float4 o = make_float4(r0 * ssv.x, r1 * ssv.y, r2 * ssv.z, r3 * ssv.w);
    *reinterpret_cast<float4*>(&out[gk * Cc + c0 + cl]) = o;

    // third output: tempAmat.T = Amat + I  (128 blocks x 128 elements)
    int lb = by * 32 + bx;           // 0..127 -> row of the 128x128 output
    if (tid < 128) {
        int idx = lb * 128 + tid;
        out[2 * PRED + idx] = Amat[idx] + (lb == tid ? 1.f : 0.f);
    }
}

extern "C" void kernel_launch(void* const* d_in, const int* in_sizes, int n_in,
                              void* d_out, int out_size)
{
    const float* x    = (const float*)d_in[0];
    const float* Amat = (const float*)d_in[1];
    const float* taus = (const float*)d_in[2];
    const float* r0   = (const float*)d_in[3];
    float* out = (float*)d_out;

    (void)in_sizes; (void)n_in; (void)out_size;

    size_t smem = (32 * SA_LD + 128 * SB_LD) * sizeof(float);  // ~51.7 KB
    cudaFuncSetAttribute(gemm_kernel, cudaFuncAttributeMaxDynamicSharedMemorySize, (int)smem);

    scan_kernel<<<Nn * Hh, 128>>>(x, taus, r0, out);
    gemm_kernel<<<dim3(32, 4), 512, smem>>>(Amat, out);
}

// round 3
// speedup vs baseline: 1.0022x; 1.0022x over previous
#include <cuda_runtime.h>

#define Nn   128
#define Hh   2
#define Ll   1024
#define Cc   (Hh * Ll)      /* 2048 columns = h*L flattened */
#define PRED (Nn * Cc)      /* 262144 */

#define SAT_LD 36           /* padded lead dim for transposed Amat tile [128][32] */
#define SB_LD  68           /* padded lead dim for alpha tile (128 x 64) */

__device__ float g_alpha[PRED];
__device__ float g_Ss[PRED];

// ---- packed fp32x2 helpers (sm_103a FFMA2 path, PTX-only) ------------------
__device__ __forceinline__ unsigned long long pack2(float lo, float hi) {
    unsigned long long r;
    asm("mov.b64 %0, {%1, %2};" : "=l"(r) : "f"(lo), "f"(hi));
    return r;
}
__device__ __forceinline__ void unpack2(unsigned long long v, float& lo, float& hi) {
    asm("mov.b64 {%0, %1}, %2;" : "=f"(lo), "=f"(hi) : "l"(v));
}
__device__ __forceinline__ unsigned long long ffma2(unsigned long long a,
                                                    unsigned long long b,
                                                    unsigned long long c) {
    unsigned long long d;
    asm("fma.rn.f32x2 %0, %1, %2, %3;" : "=l"(d) : "l"(a), "l"(b), "l"(c));
    return d;
}

// ---------------------------------------------------------------------------
// Kernel 1: per-(n,h)-row fused relu + cumsum + exponential-decay recurrence.
// ---------------------------------------------------------------------------
__global__ void __launch_bounds__(128) scan_kernel(const float* __restrict__ x,
                                                   const float* __restrict__ taus,
                                                   const float* __restrict__ r0dt,
                                                   float* __restrict__ out)
{
    int row  = blockIdx.x;          // n*H + h
    int t    = threadIdx.x;         // 0..127
    int lane = t & 31, wid = t >> 5;
    int base = row * Ll + t * 8;

    const float4* xv = reinterpret_cast<const float4*>(x + base);
    float4 v0 = xv[0], v1 = xv[1];
    float s[8] = { fmaxf(v0.x, 0.f), fmaxf(v0.y, 0.f), fmaxf(v0.z, 0.f), fmaxf(v0.w, 0.f),
                   fmaxf(v1.x, 0.f), fmaxf(v1.y, 0.f), fmaxf(v1.z, 0.f), fmaxf(v1.w, 0.f) };

    float tau = taus[row];
    float R0  = r0dt[row];
    float d   = 1.f - 1.f / tau;

    float cum = 0.f, isv = 0.f;
#pragma unroll
    for (int k = 0; k < 8; k++) { cum += s[k]; isv = fmaf(d, isv, s[k]); }

    float d2 = d * d, d4 = d2 * d2, r8 = d4 * d4;   // d^8

    float inclI = isv, inclC = cum, rp = r8;
#pragma unroll
    for (int off = 1; off < 32; off <<= 1) {
        float ui = __shfl_up_sync(0xffffffffu, inclI, off);
        float uc = __shfl_up_sync(0xffffffffu, inclC, off);
        if (lane >= off) { inclI = fmaf(rp, ui, inclI); inclC += uc; }
        rp *= rp;
    }

    __shared__ float wI[4], wC[4];
    if (lane == 31) { wI[wid] = inclI; wC[wid] = inclC; }
    __syncthreads();

    float Rw = rp;                                  // d^256
    float exI = 0.f, exC = 0.f, aI = 0.f, aC = 0.f;
#pragma unroll
    for (int w = 0; w < 4; w++) {
        if (w == wid) { exI = aI; exC = aC; }
        aI = fmaf(Rw, aI, wI[w]);
        aC += wC[w];
    }

    float upI = __shfl_up_sync(0xffffffffu, inclI, 1);
    float upC = __shfl_up_sync(0xffffffffu, inclC, 1);
    if (lane == 0) { upI = 0.f; upC = 0.f; }
    float XI = fmaf(exI, __powf(r8, (float)lane), upI);
    float XC = upC + exC;

    float al[8], ss[8];
    float ci = XI, cc = XC;
#pragma unroll
    for (int k = 0; k < 8; k++) {
        ci = fmaf(d, ci, s[k]);
        cc += s[k];
        al[k] = 1.f - __expf(-R0 * ci);
        ss[k] = 1.f - cc;
    }

    float4* ga = reinterpret_cast<float4*>(g_alpha + base);
    ga[0] = make_float4(al[0], al[1], al[2], al[3]);
    ga[1] = make_float4(al[4], al[5], al[6], al[7]);
    float4* gs = reinterpret_cast<float4*>(g_Ss + base);
    gs[0] = make_float4(ss[0], ss[1], ss[2], ss[3]);
    gs[1] = make_float4(ss[4], ss[5], ss[6], ss[7]);
    float4* go = reinterpret_cast<float4*>(out + PRED + base);   // signal output
    go[0] = make_float4(s[0], s[1], s[2], s[3]);
    go[1] = make_float4(s[4], s[5], s[6], s[7]);
}

// ---------------------------------------------------------------------------
// Kernel 2: Alpha = alpha + Amat @ alpha ;  pred = Alpha * Ss ; plus Amat + I.
// Grid (32 col-tiles x 4 row-tiles); block tile 32 rows x 64 cols; 128 threads,
// thread tile 4 rows x 4 cols = 16 accs as 8 packed f32x2 (FFMA2).
// Amat tile stored TRANSPOSED in smem so 4 row-coeffs come from one LDS.128.
// ---------------------------------------------------------------------------
__global__ void __launch_bounds__(128) gemm_kernel(const float* __restrict__ Amat,
                                                   float* __restrict__ out)
{
    extern __shared__ float sm[];
    float* sAT = sm;                   // [128][SAT_LD]: sAT[m][k] = Amat[k0+k][m]
    float* sB  = sm + 128 * SAT_LD;    // [128][SB_LD]: all m, 64 local cols

    int bx = blockIdx.x;               // 64-col tile (0..31)
    int by = blockIdx.y;               // 32-row tile (0..3)
    int tid = threadIdx.x;
    int k0 = by * 32, c0 = bx * 64;

#pragma unroll
    for (int i = tid; i < 32 * 128; i += 128) {
        int k = i >> 7, m = i & 127;                 // coalesced global read
        sAT[m * SAT_LD + k] = Amat[(k0 + k) * 128 + m];
    }
#pragma unroll
    for (int i = tid; i < 128 * 16; i += 128) {
        int m = i >> 4, cq = i & 15;
        float4 v = *reinterpret_cast<const float4*>(&g_alpha[m * Cc + c0 + cq * 4]);
        *reinterpret_cast<float4*>(&sB[m * SB_LD + cq * 4]) = v;
    }
    __syncthreads();

    int tx = tid & 15;                 // col quad: local cols tx*4 .. +3
    int ty = tid >> 4;                 // row quad: local rows ty*4 .. +3
    int kr = 4 * ty;
    int cl = 4 * tx;

    // identity seed: Alpha = alpha + Amat@alpha  (rows k0+kr.. live in sB)
    unsigned long long acc[4][2];
#pragma unroll
    for (int r = 0; r < 4; r++) {
        float4 iv = *reinterpret_cast<float4*>(&sB[(k0 + kr + r) * SB_LD + cl]);
        acc[r][0] = pack2(iv.x, iv.y);
        acc[r][1] = pack2(iv.z, iv.w);
    }

#pragma unroll 4
    for (int m = 0; m < 128; m++) {
        float4 bv = *reinterpret_cast<float4*>(&sB[m * SB_LD + cl]);
        float4 av = *reinterpret_cast<float4*>(&sAT[m * SAT_LD + kr]);
        unsigned long long bp0 = pack2(bv.x, bv.y);
        unsigned long long bp1 = pack2(bv.z, bv.w);
        unsigned long long a0 = pack2(av.x, av.x);
        unsigned long long a1 = pack2(av.y, av.y);
        unsigned long long a2 = pack2(av.z, av.z);
        unsigned long long a3 = pack2(av.w, av.w);
        acc[0][0] = ffma2(a0, bp0, acc[0][0]);  acc[0][1] = ffma2(a0, bp1, acc[0][1]);
        acc[1][0] = ffma2(a1, bp0, acc[1][0]);  acc[1][1] = ffma2(a1, bp1, acc[1][1]);
        acc[2][0] = ffma2(a2, bp0, acc[2][0]);  acc[2][1] = ffma2(a2, bp1, acc[2][1]);
        acc[3][0] = ffma2(a3, bp0, acc[3][0]);  acc[3][1] = ffma2(a3, bp1, acc[3][1]);
    }

#pragma unroll
    for (int r = 0; r < 4; r++) {
        int gk = k0 + kr + r;
        const float4 ssv = *reinterpret_cast<const float4*>(&g_Ss[gk * Cc + c0 + cl]);
        float r0, r1, r2, r3;
        unpack2(acc[r][0], r0, r1);
        unpack2(acc[r][1], r2, r3);
        float4 o = make_float4(r0 * ssv.x, r1 * ssv.y, r2 * ssv.z, r3 * ssv.w);
        *reinterpret_cast<float4*>(&out[gk * Cc + c0 + cl]) = o;
    }

    // third output: tempAmat.T = Amat + I  (128 blocks x 128 elements)
    int lb = by * 32 + bx;             // 0..127 -> row of the 128x128 output
    {
        int idx = lb * 128 + tid;
        out[2 * PRED + idx] = Amat[idx] + (lb == tid ? 1.f : 0.f);
    }
}

extern "C" void kernel_launch(void* const* d_in, const int* in_sizes, int n_in,
                              void* d_out, int out_size)
{
    const float* x    = (const float*)d_in[0];
    const float* Amat = (const float*)d_in[1];
    const float* taus = (const float*)d_in[2];
    const float* r0   = (const float*)d_in[3];
    float* out = (float*)d_out;

    (void)in_sizes; (void)n_in; (void)out_size;

    size_t smem = (128 * SAT_LD + 128 * SB_LD) * sizeof(float);  // ~53.2 KB
    cudaFuncSetAttribute(gemm_kernel, cudaFuncAttributeMaxDynamicSharedMemorySize, (int)smem);

    scan_kernel<<<Nn * Hh, 128>>>(x, taus, r0, out);
    gemm_kernel<<<dim3(32, 4), 128, smem>>>(Amat, out);
}

// round 4
// speedup vs baseline: 1.1373x; 1.1348x over previous
#include <cuda_runtime.h>

#define Nn   128
#define Hh   2
#define Ll   1024
#define Cc   (Hh * Ll)      /* 2048 columns = h*L flattened */
#define PRED (Nn * Cc)      /* 262144 */

#define SAT_LD 18           /* [m][k] transposed Amat tile: 128 x 16, pad 18 */
#define SB_LD  68           /* [m][c] alpha tile: 128 x 64, pad 68 */

__device__ float g_alpha[PRED];
__device__ float g_Ss[PRED];

// ---- packed fp32x2 helpers (sm_103a FFMA2 path, PTX-only) ------------------
__device__ __forceinline__ unsigned long long pack2(float lo, float hi) {
    unsigned long long r;
    asm("mov.b64 %0, {%1, %2};" : "=l"(r) : "f"(lo), "f"(hi));
    return r;
}
__device__ __forceinline__ void unpack2(unsigned long long v, float& lo, float& hi) {
    asm("mov.b64 {%0, %1}, %2;" : "=f"(lo), "=f"(hi) : "l"(v));
}
__device__ __forceinline__ unsigned long long ffma2(unsigned long long a,
                                                    unsigned long long b,
                                                    unsigned long long c) {
    unsigned long long d;
    asm("fma.rn.f32x2 %0, %1, %2, %3;" : "=l"(d) : "l"(a), "l"(b), "l"(c));
    return d;
}

// ---------------------------------------------------------------------------
// Kernel 1: per-(n,h)-row fused relu + cumsum + exponential-decay recurrence.
// Also emits the third output (Amat + I), which needs no scan data.
// ---------------------------------------------------------------------------
__global__ void __launch_bounds__(128) scan_kernel(const float* __restrict__ x,
                                                   const float* __restrict__ Amat,
                                                   const float* __restrict__ taus,
                                                   const float* __restrict__ r0dt,
                                                   float* __restrict__ out)
{
    int row  = blockIdx.x;          // n*H + h
    int t    = threadIdx.x;         // 0..127
    int lane = t & 31, wid = t >> 5;
    int base = row * Ll + t * 8;

    const float4* xv = reinterpret_cast<const float4*>(x + base);
    float4 v0 = xv[0], v1 = xv[1];
    float s[8] = { fmaxf(v0.x, 0.f), fmaxf(v0.y, 0.f), fmaxf(v0.z, 0.f), fmaxf(v0.w, 0.f),
                   fmaxf(v1.x, 0.f), fmaxf(v1.y, 0.f), fmaxf(v1.z, 0.f), fmaxf(v1.w, 0.f) };

    // third output: tempAmat.T = Amat + I  (first 128 blocks each do one row)
    if (row < 128) {
        int idx = row * 128 + t;
        out[2 * PRED + idx] = Amat[idx] + (row == t ? 1.f : 0.f);
    }

    float tau = taus[row];
    float R0  = r0dt[row];
    float d   = 1.f - 1.f / tau;

    float cum = 0.f, isv = 0.f;
#pragma unroll
    for (int k = 0; k < 8; k++) { cum += s[k]; isv = fmaf(d, isv, s[k]); }

    float d2 = d * d, d4 = d2 * d2, r8 = d4 * d4;   // d^8

    float inclI = isv, inclC = cum, rp = r8;
#pragma unroll
    for (int off = 1; off < 32; off <<= 1) {
        float ui = __shfl_up_sync(0xffffffffu, inclI, off);
        float uc = __shfl_up_sync(0xffffffffu, inclC, off);
        if (lane >= off) { inclI = fmaf(rp, ui, inclI); inclC += uc; }
        rp *= rp;
    }

    __shared__ float wI[4], wC[4];
    if (lane == 31) { wI[wid] = inclI; wC[wid] = inclC; }
    __syncthreads();

    float Rw = rp;                                  // d^256
    float exI = 0.f, exC = 0.f, aI = 0.f, aC = 0.f;
#pragma unroll
    for (int w = 0; w < 4; w++) {
        if (w == wid) { exI = aI; exC = aC; }
        aI = fmaf(Rw, aI, wI[w]);
        aC += wC[w];
    }

    float upI = __shfl_up_sync(0xffffffffu, inclI, 1);
    float upC = __shfl_up_sync(0xffffffffu, inclC, 1);
    if (lane == 0) { upI = 0.f; upC = 0.f; }
    float XI = fmaf(exI, __powf(r8, (float)lane), upI);
    float XC = upC + exC;

    float al[8], ss[8];
    float ci = XI, cc = XC;
#pragma unroll
    for (int k = 0; k < 8; k++) {
        ci = fmaf(d, ci, s[k]);
        cc += s[k];
        al[k] = 1.f - __expf(-R0 * ci);
        ss[k] = 1.f - cc;
    }

    float4* ga = reinterpret_cast<float4*>(g_alpha + base);
    ga[0] = make_float4(al[0], al[1], al[2], al[3]);
    ga[1] = make_float4(al[4], al[5], al[6], al[7]);
    float4* gs = reinterpret_cast<float4*>(g_Ss + base);
    gs[0] = make_float4(ss[0], ss[1], ss[2], ss[3]);
    gs[1] = make_float4(ss[4], ss[5], ss[6], ss[7]);
    float4* go = reinterpret_cast<float4*>(out + PRED + base);   // signal output
    go[0] = make_float4(s[0], s[1], s[2], s[3]);
    go[1] = make_float4(s[4], s[5], s[6], s[7]);
}

// ---------------------------------------------------------------------------
// Kernel 2: Alpha = alpha + Amat @ alpha ;  pred = Alpha * Ss.
// Grid (32 col-tiles x 8 row-tiles) = 256 blocks; block tile 16 rows x 64
// cols; 128 threads; thread tile 2 rows x 4 cols (4 packed f32x2 accs).
// ---------------------------------------------------------------------------
__global__ void __launch_bounds__(128, 2) gemm_kernel(const float* __restrict__ Amat,
                                                      float* __restrict__ out)
{
    __shared__ float sAT[128 * SAT_LD];   // sAT[m][k] = Amat[k0+k][m]
    __shared__ float sB[128 * SB_LD];     // sB[m][c]  = alpha[m][c0+c]

    int bx = blockIdx.x;               // 64-col tile (0..31)
    int by = blockIdx.y;               // 16-row tile (0..7)
    int tid = threadIdx.x;
    int k0 = by * 16, c0 = bx * 64;

    // fill sAT (transposed, coalesced LDG)
#pragma unroll
    for (int k = 0; k < 16; k++)
        sAT[tid * SAT_LD + k] = Amat[(k0 + k) * 128 + tid];

    // fill sB: 2048 float4 quads / 128 threads = 16 iters
#pragma unroll
    for (int j = 0; j < 16; j++) {
        int i = j * 128 + tid;
        int m = i >> 4, cq = i & 15;
        float4 v = *reinterpret_cast<const float4*>(&g_alpha[m * Cc + c0 + cq * 4]);
        *reinterpret_cast<float4*>(&sB[m * SB_LD + cq * 4]) = v;
    }
    __syncthreads();

    int tx = tid & 15;                 // col quad: local cols 4*tx .. +3
    int ty = tid >> 4;                 // row pair: local rows 2*ty, 2*ty+1
    int kr = 2 * ty;
    int cl = 4 * tx;

    // identity seed: Alpha = alpha + Amat@alpha  (rows k0+kr,+1 live in sB)
    float4 i0 = *reinterpret_cast<float4*>(&sB[(k0 + kr)     * SB_LD + cl]);
    float4 i1 = *reinterpret_cast<float4*>(&sB[(k0 + kr + 1) * SB_LD + cl]);
    unsigned long long acc00 = pack2(i0.x, i0.y), acc01 = pack2(i0.z, i0.w);
    unsigned long long acc10 = pack2(i1.x, i1.y), acc11 = pack2(i1.z, i1.w);

#pragma unroll 8
    for (int m = 0; m < 128; m++) {
        float4 bv = *reinterpret_cast<float4*>(&sB[m * SB_LD + cl]);
        float2 av = *reinterpret_cast<float2*>(&sAT[m * SAT_LD + kr]);
        unsigned long long bp0 = pack2(bv.x, bv.y);
        unsigned long long bp1 = pack2(bv.z, bv.w);
        unsigned long long a0  = pack2(av.x, av.x);
        unsigned long long a1  = pack2(av.y, av.y);
        acc00 = ffma2(a0, bp0, acc00);  acc01 = ffma2(a0, bp1, acc01);
        acc10 = ffma2(a1, bp0, acc10);  acc11 = ffma2(a1, bp1, acc11);
    }

    {
        int gk = k0 + kr;
        const float4 ssv = *reinterpret_cast<const float4*>(&g_Ss[gk * Cc + c0 + cl]);
        float r0, r1, r2, r3;
        unpack2(acc00, r0, r1);
        unpack2(acc01, r2, r3);
        float4 o = make_float4(r0 * ssv.x, r1 * ssv.y, r2 * ssv.z, r3 * ssv.w);
        *reinterpret_cast<float4*>(&out[gk * Cc + c0 + cl]) = o;
    }
    {
        int gk = k0 + kr + 1;
        const float4 ssv = *reinterpret_cast<const float4*>(&g_Ss[gk * Cc + c0 + cl]);
        float r0, r1, r2, r3;
        unpack2(acc10, r0, r1);
        unpack2(acc11, r2, r3);
        float4 o = make_float4(r0 * ssv.x, r1 * ssv.y, r2 * ssv.z, r3 * ssv.w);
        *reinterpret_cast<float4*>(&out[gk * Cc + c0 + cl]) = o;
    }
}

extern "C" void kernel_launch(void* const* d_in, const int* in_sizes, int n_in,
                              void* d_out, int out_size)
{
    const float* x    = (const float*)d_in[0];
    const float* Amat = (const float*)d_in[1];
    const float* taus = (const float*)d_in[2];
    const float* r0   = (const float*)d_in[3];
    float* out = (float*)d_out;

    (void)in_sizes; (void)n_in; (void)out_size;

    scan_kernel<<<Nn * Hh, 128>>>(x, Amat, taus, r0, out);
    gemm_kernel<<<dim3(32, 8), 128>>>(Amat, out);
}